// round 5
// baseline (speedup 1.0000x reference)
#include <cuda_runtime.h>
#include <math.h>

// ---------------- simulation constants (mirror reference) ----------------
#define NP          4096
#define BLOCK       128
#define TI          4                     // particles (i) per block
#define NBLK        (NP / TI)             // 1024 blocks
#define NROW        (NP / BLOCK)          // 32 j-rows per block
#define RADIUS_C    0.1f
#define DT_C        (1.0f/60.0f)
#define INV_DT_C    60.0f
#define MAX_VEL_C   3.0f                  // 0.5*0.1/DT
#define VISC_C      60.0f
#define REST_C      17510.1f
#define STIFF_C     2.99e-11f
#define EPS_C       1e-8f
// 15 / (pi * R^6)
#define SPIKY_C     (15.0f / (3.14159265358979323846f * 1e-6f))
// conservative active-pair guard: t>0 implies d2e < R^2*(1+~2^-20); margin 1e-4
#define R2_GUARD    (RADIUS_C * RADIUS_C * 1.0001f)

// ---------------- scratch state (no allocations allowed) -----------------
__device__ float4 g_predA[NP];
__device__ float4 g_predB[NP];
__device__ float4 g_vel[NP];     // raw new_vel before viscosity smoothing
// per (block, j-row, warp) activity byte, written by rho, reused by delta
__device__ unsigned char g_mask[NBLK][NROW][4];

// ---------------- reductions ----------------
__device__ __forceinline__ float warp_sum(float v) {
    #pragma unroll
    for (int o = 16; o > 0; o >>= 1) v += __shfl_xor_sync(0xFFFFFFFFu, v, o);
    return v;
}

// Reduce V (<=16) per-thread values across a 128-thread block.
// Results land in tot[0..V) (shared). All threads sync'd on exit.
template <int V>
__device__ __forceinline__ void block_reduceV(float* v, float* tot) {
    __shared__ float s[4][16];
    int w = threadIdx.x >> 5, l = threadIdx.x & 31;
    #pragma unroll
    for (int k = 0; k < V; k++) v[k] = warp_sum(v[k]);
    if (l == 0) {
        #pragma unroll
        for (int k = 0; k < V; k++) s[w][k] = v[k];
    }
    __syncthreads();
    if (threadIdx.x < V)
        tot[threadIdx.x] = s[0][threadIdx.x] + s[1][threadIdx.x]
                         + s[2][threadIdx.x] + s[3][threadIdx.x];
    __syncthreads();
}

__device__ __forceinline__ float3 cap_mag(float x, float y, float z) {
    float vv = sqrtf(x*x + y*y + z*z);
    float s  = fminf(MAX_VEL_C / (vv + 1e-4f), 1.0f);
    return make_float3(x*s, y*s, z*s);
}

// ---------------- kernels ----------------
__global__ void init_kernel(const float* __restrict__ locs,
                            const float* __restrict__ vel) {
    int i = blockIdx.x * blockDim.x + threadIdx.x;
    if (i >= NP) return;
    float vx = vel[3*i+0];
    float vy = vel[3*i+1] - 9.8f * DT_C;
    float vz = vel[3*i+2];
    float3 v = cap_mag(vx, vy, vz);
    g_predA[i] = make_float4(locs[3*i+0] + DT_C * v.x,
                             locs[3*i+1] + DT_C * v.y,
                             locs[3*i+2] + DT_C * v.z, 0.0f);
}

// density + lambda for TI particles per block.
// Stores the PRE-SCALED lambda' = -3*SPIKY_C*lambda into buf[i].w.
// Also records, per (j-row, warp), whether ANY of the 128 covered pairs is
// active — delta_kernel (same positions!) reuses this to skip rows wholesale.
__global__ void __launch_bounds__(BLOCK) rho_kernel(int useA) {
    float4* buf = useA ? g_predA : g_predB;
    int i0 = blockIdx.x * TI;
    float4 p[TI];
    #pragma unroll
    for (int k = 0; k < TI; k++) p[k] = buf[i0 + k];

    float sum[TI] = {0.f, 0.f, 0.f, 0.f};   // unscaled sum of t^3
    for (int it = 0, j = threadIdx.x; j < NP; it++, j += BLOCK) {
        float4 q = buf[j];
        float d2e[TI];
        #pragma unroll
        for (int k = 0; k < TI; k++) {
            float dx = p[k].x - q.x, dy = p[k].y - q.y, dz = p[k].z - q.z;
            d2e[k] = fmaf(dx, dx, fmaf(dy, dy, fmaf(dz, dz, EPS_C)));
        }
        float mn = fminf(fminf(d2e[0], d2e[1]), fminf(d2e[2], d2e[3]));
        unsigned int vote = __any_sync(0xFFFFFFFFu, mn < R2_GUARD);
        if ((threadIdx.x & 31) == 0)
            g_mask[blockIdx.x][it][threadIdx.x >> 5] = (unsigned char)vote;
        if (vote) {
            #pragma unroll
            for (int k = 0; k < TI; k++) {
                float rinv = rsqrtf(d2e[k]);
                float t = fmaxf(fmaf(-d2e[k], rinv, RADIUS_C), 0.0f); // max(R-d,0)
                sum[k] = fmaf(t * t, t, sum[k]);
            }
        }
    }
    __shared__ float tot[16];
    block_reduceV<TI>(sum, tot);
    if (threadIdx.x < TI) {
        // self term (dx=dy=dz=0), computed with the identical op sequence
        float rs = rsqrtf(EPS_C);
        float ts = fmaxf(fmaf(-EPS_C, rs, RADIUS_C), 0.0f);
        float rho = (tot[threadIdx.x] - (ts * ts) * ts) * SPIKY_C;
        float lam = -(rho - REST_C) * STIFF_C;
        buf[i0 + threadIdx.x].w = lam * (-3.0f * SPIKY_C);      // pre-scaled
    }
}

// position correction; reads inA buffer (pos + pre-scaled lambda), writes other.
// Reuses g_mask from the immediately preceding rho pass (same positions, same
// block/row/warp -> j mapping) to skip inactive rows before any load/math.
__global__ void __launch_bounds__(BLOCK) delta_kernel(int inA, int last,
                                                      const float* __restrict__ locs,
                                                      float* __restrict__ out_pred) {
    const float4* in   = inA ? g_predA : g_predB;
    float4*       outb = inA ? g_predB : g_predA;
    int i0 = blockIdx.x * TI;
    int w = threadIdx.x >> 5;
    float4 p[TI];
    #pragma unroll
    for (int k = 0; k < TI; k++) p[k] = in[i0 + k];

    float acc[TI * 3];
    #pragma unroll
    for (int k = 0; k < TI * 3; k++) acc[k] = 0.f;

    for (int it = 0, j = threadIdx.x; j < NP; it++, j += BLOCK) {
        if (g_mask[blockIdx.x][it][w]) {
            float4 q = in[j];
            #pragma unroll
            for (int k = 0; k < TI; k++) {
                float dx = p[k].x - q.x, dy = p[k].y - q.y, dz = p[k].z - q.z;
                float d2e = fmaf(dx, dx, fmaf(dy, dy, fmaf(dz, dz, EPS_C)));
                float rinv = rsqrtf(d2e);
                float t = fmaxf(fmaf(-d2e, rinv, RADIUS_C), 0.0f);
                // self pair: diff = 0 -> contributes 0 regardless of c
                float c = ((p[k].w + q.w) * (t * t)) * rinv;
                acc[3*k+0] = fmaf(c, dx, acc[3*k+0]);
                acc[3*k+1] = fmaf(c, dy, acc[3*k+1]);
                acc[3*k+2] = fmaf(c, dz, acc[3*k+2]);
            }
        }
    }
    __shared__ float tot[16];
    block_reduceV<TI * 3>(acc, tot);
    if (threadIdx.x < TI) {
        int k = threadIdx.x, i = i0 + k;
        float nx = p[k].x + tot[3*k+0];              // RELAXATION = 1
        float ny = p[k].y + tot[3*k+1];
        float nz = p[k].z + tot[3*k+2];
        outb[i] = make_float4(nx, ny, nz, 0.0f);
        if (last) {
            g_vel[i] = make_float4((nx - locs[3*i+0]) * INV_DT_C,
                                   (ny - locs[3*i+1]) * INV_DT_C,
                                   (nz - locs[3*i+2]) * INV_DT_C, 0.0f);
            out_pred[3*i+0] = nx;
            out_pred[3*i+1] = ny;
            out_pred[3*i+2] = nz;
        }
    }
}

// XSPH viscosity on final positions (g_predB) + raw velocities (g_vel).
// Positions differ from the last rho pass, so it uses its own combined vote.
// Accumulates UNSCALED t^3 sums; SPIKY_C folds into the epilogue constant.
// Self term cancels exactly in (sum_j w v_j) - wsum*v_i.
__global__ void __launch_bounds__(BLOCK) visc_kernel(float* __restrict__ out_vel) {
    int i0 = blockIdx.x * TI;
    float4 p[TI];
    #pragma unroll
    for (int k = 0; k < TI; k++) p[k] = g_predB[i0 + k];

    float acc[TI * 4];                               // wsum, wx, wy, wz per i
    #pragma unroll
    for (int k = 0; k < TI * 4; k++) acc[k] = 0.f;

    for (int j = threadIdx.x; j < NP; j += BLOCK) {
        float4 q = g_predB[j];
        float d2e[TI];
        #pragma unroll
        for (int k = 0; k < TI; k++) {
            float dx = p[k].x - q.x, dy = p[k].y - q.y, dz = p[k].z - q.z;
            d2e[k] = fmaf(dx, dx, fmaf(dy, dy, fmaf(dz, dz, EPS_C)));
        }
        float mn = fminf(fminf(d2e[0], d2e[1]), fminf(d2e[2], d2e[3]));
        if (__any_sync(0xFFFFFFFFu, mn < R2_GUARD)) {
            float4 vj = g_vel[j];                    // only load vel when needed
            #pragma unroll
            for (int k = 0; k < TI; k++) {
                float rinv = rsqrtf(d2e[k]);
                float t = fmaxf(fmaf(-d2e[k], rinv, RADIUS_C), 0.0f);
                float wgt = (t * t) * t;             // unscaled
                acc[4*k+0] += wgt;
                acc[4*k+1] = fmaf(wgt, vj.x, acc[4*k+1]);
                acc[4*k+2] = fmaf(wgt, vj.y, acc[4*k+2]);
                acc[4*k+3] = fmaf(wgt, vj.z, acc[4*k+3]);
            }
        }
    }
    __shared__ float tot[16];
    block_reduceV<TI * 4>(acc, tot);
    if (threadIdx.x < TI) {
        int k = threadIdx.x, i = i0 + k;
        float4 v = g_vel[i];
        const float kk = (VISC_C * DT_C / REST_C) * SPIKY_C;  // fold spiky scale
        float wsum = tot[4*k+0];
        float nx = v.x + kk * (tot[4*k+1] - wsum * v.x);
        float ny = v.y + kk * (tot[4*k+2] - wsum * v.y);
        float nz = v.z + kk * (tot[4*k+3] - wsum * v.z);
        float3 c = cap_mag(nx, ny, nz);
        out_vel[3*i+0] = c.x;
        out_vel[3*i+1] = c.y;
        out_vel[3*i+2] = c.z;
    }
}

// ---------------- launcher ----------------
extern "C" void kernel_launch(void* const* d_in, const int* in_sizes, int n_in,
                              void* d_out, int out_size) {
    const float* locs = (const float*)d_in[0];
    const float* vel  = (const float*)d_in[1];
    float* out = (float*)d_out;
    float* out_pred = out;                 // [1,4096,3]
    float* out_vel  = out + 3 * NP;        // [1,4096,3]

    init_kernel<<<(NP + BLOCK - 1) / BLOCK, BLOCK>>>(locs, vel);

    // iter 1: A -> B
    rho_kernel<<<NBLK, BLOCK>>>(1);
    delta_kernel<<<NBLK, BLOCK>>>(1, 0, locs, out_pred);
    // iter 2: B -> A
    rho_kernel<<<NBLK, BLOCK>>>(0);
    delta_kernel<<<NBLK, BLOCK>>>(0, 0, locs, out_pred);
    // iter 3: A -> B (final), also emit pred + raw new_vel
    rho_kernel<<<NBLK, BLOCK>>>(1);
    delta_kernel<<<NBLK, BLOCK>>>(1, 1, locs, out_pred);

    visc_kernel<<<NBLK, BLOCK>>>(out_vel);
}

// round 7
// speedup vs baseline: 1.1142x; 1.1142x over previous
#include <cuda_runtime.h>
#include <math.h>

// ---------------- simulation constants (mirror reference) ----------------
#define NP          4096
#define NC          10                    // cells per axis (cell size = RADIUS)
#define NCELL       (NC * NC * NC)        // 1000
#define RADIUS_C    0.1f
#define DT_C        (1.0f/60.0f)
#define INV_DT_C    60.0f
#define MAX_VEL_C   3.0f                  // 0.5*0.1/DT
#define VISC_C      60.0f
#define REST_C      17510.1f
#define STIFF_C     2.99e-11f
#define EPS_C       1e-8f
// 15 / (pi * R^6)
#define SPIKY_C     (15.0f / (3.14159265358979323846f * 1e-6f))

#define PASS_BLOCK  256                   // 8 warps; warp-per-particle passes
#define PASS_GRID   (NP / (PASS_BLOCK / 32))   // 512 blocks

// ---------------- scratch state (no allocations allowed) -----------------
__device__ float4 g_posTmp[NP];   // canonical UNSORTED positions (w unused)
__device__ float4 g_pos[NP];      // cell-sorted positions; .w carries lambda'
__device__ float4 g_velS[NP];     // cell-sorted raw velocities (visc pass)
__device__ float4 g_vel[NP];      // unsorted raw new_vel (written by last delta)
__device__ int    g_cid[NP];      // cell id per unsorted particle
__device__ int    g_origIdx[NP];  // sorted slot -> original index
__device__ int    g_hist[1024];   // zero at load; scan re-zeroes each use
__device__ int    g_cellStart[NCELL + 1];
__device__ int    g_cursor[NCELL];

// ---------------- helpers ----------------
__device__ __forceinline__ int clampi(int v, int lo, int hi) {
    return v < lo ? lo : (v > hi ? hi : v);
}
__device__ __forceinline__ int cellId(float x, float y, float z) {
    int cx = clampi(__float2int_rd(x * (float)NC), 0, NC - 1);
    int cy = clampi(__float2int_rd(y * (float)NC), 0, NC - 1);
    int cz = clampi(__float2int_rd(z * (float)NC), 0, NC - 1);
    return (cz * NC + cy) * NC + cx;
}
__device__ __forceinline__ void cellCoord(float x, float y, float z,
                                          int& cx, int& cy, int& cz) {
    cx = clampi(__float2int_rd(x * (float)NC), 0, NC - 1);
    cy = clampi(__float2int_rd(y * (float)NC), 0, NC - 1);
    cz = clampi(__float2int_rd(z * (float)NC), 0, NC - 1);
}
__device__ __forceinline__ float warp_sum(float v) {
    #pragma unroll
    for (int o = 16; o > 0; o >>= 1) v += __shfl_xor_sync(0xFFFFFFFFu, v, o);
    return v;
}
__device__ __forceinline__ float3 cap_mag(float x, float y, float z) {
    float vv = sqrtf(x*x + y*y + z*z);
    float s  = fminf(MAX_VEL_C / (vv + 1e-4f), 1.0f);
    return make_float3(x*s, y*s, z*s);
}

// ---------------- kernels ----------------
// external force + clamp + predict; also histograms the predicted positions
__global__ void init_kernel(const float* __restrict__ locs,
                            const float* __restrict__ vel) {
    int i = blockIdx.x * blockDim.x + threadIdx.x;
    if (i >= NP) return;
    float vx = vel[3*i+0];
    float vy = vel[3*i+1] - 9.8f * DT_C;
    float vz = vel[3*i+2];
    float3 v = cap_mag(vx, vy, vz);
    float nx = locs[3*i+0] + DT_C * v.x;
    float ny = locs[3*i+1] + DT_C * v.y;
    float nz = locs[3*i+2] + DT_C * v.z;
    g_posTmp[i] = make_float4(nx, ny, nz, 0.0f);
    int cid = cellId(nx, ny, nz);
    g_cid[i] = cid;
    atomicAdd(&g_hist[cid], 1);
}

// exclusive scan of the (already-populated) histogram; single block.
// Re-zeroes g_hist so the NEXT producer pass (init/delta) can histogram again.
__global__ void __launch_bounds__(1024) scan_kernel() {
    __shared__ int ssum[1024];
    int tid = threadIdx.x;
    int v = g_hist[tid];
    g_hist[tid] = 0;                        // reset for next build
    ssum[tid] = v;
    __syncthreads();
    #pragma unroll
    for (int off = 1; off < 1024; off <<= 1) {
        int t = (tid >= off) ? ssum[tid - off] : 0;
        __syncthreads();
        ssum[tid] += t;
        __syncthreads();
    }
    int excl = ssum[tid] - v;               // exclusive scan
    if (tid < NCELL) { g_cellStart[tid] = excl; g_cursor[tid] = excl; }
    if (tid == NCELL) g_cellStart[NCELL] = excl;   // == NP (cells>=1000 empty)
}

// scatter into cell-sorted order; optionally gather velocities too
__global__ void scatter_kernel(int copyVel) {
    int i = blockIdx.x * blockDim.x + threadIdx.x;
    if (i >= NP) return;
    int cid  = g_cid[i];
    int slot = atomicAdd(&g_cursor[cid], 1);
    float4 p = g_posTmp[i];
    g_pos[slot] = make_float4(p.x, p.y, p.z, 0.0f);
    g_origIdx[slot] = i;
    if (copyVel) g_velS[slot] = g_vel[i];
}

// density + lambda, warp per sorted slot; writes pre-scaled lambda into .w
__global__ void __launch_bounds__(PASS_BLOCK) rho_cell_kernel() {
    int wi   = blockIdx.x * (PASS_BLOCK / 32) + (threadIdx.x >> 5);
    int lane = threadIdx.x & 31;
    float4 p = g_pos[wi];
    int cx, cy, cz; cellCoord(p.x, p.y, p.z, cx, cy, cz);
    float sum = 0.0f;                       // unscaled sum of t^3 (incl. self)
    int x0 = cx > 0 ? cx - 1 : 0;
    int x1 = cx < NC - 1 ? cx + 1 : NC - 1;
    #pragma unroll
    for (int dz = -1; dz <= 1; dz++) {
        int z = cz + dz; if (z < 0 || z >= NC) continue;
        #pragma unroll
        for (int dy = -1; dy <= 1; dy++) {
            int y = cy + dy; if (y < 0 || y >= NC) continue;
            int c0 = (z * NC + y) * NC + x0;
            int s = g_cellStart[c0];
            int e = g_cellStart[c0 + (x1 - x0) + 1];
            for (int j = s + lane; j < e; j += 32) {
                float4 q = g_pos[j];
                float dx = p.x - q.x, dyv = p.y - q.y, dzv = p.z - q.z;
                float d2e = fmaf(dx, dx, fmaf(dyv, dyv, fmaf(dzv, dzv, EPS_C)));
                float rinv = rsqrtf(d2e);
                float t = fmaxf(fmaf(-d2e, rinv, RADIUS_C), 0.0f); // max(R-d,0)
                sum = fmaf(t * t, t, sum);
            }
        }
    }
    sum = warp_sum(sum);
    if (lane == 0) {
        // subtract self term (dx=dy=dz=0 -> d2e = EPS_C), identical op sequence
        float rs = rsqrtf(EPS_C);
        float ts = fmaxf(fmaf(-EPS_C, rs, RADIUS_C), 0.0f);
        float rho = (sum - (ts * ts) * ts) * SPIKY_C;
        float lam = -(rho - REST_C) * STIFF_C;
        g_pos[wi].w = lam * (-3.0f * SPIKY_C);      // pre-scaled lambda'
    }
}

// position correction, warp per sorted slot; writes unsorted g_posTmp and
// histograms the NEW position for the next build (scan re-zeroed g_hist).
__global__ void __launch_bounds__(PASS_BLOCK) delta_cell_kernel(
        int last, const float* __restrict__ locs, float* __restrict__ out_pred) {
    int wi   = blockIdx.x * (PASS_BLOCK / 32) + (threadIdx.x >> 5);
    int lane = threadIdx.x & 31;
    float4 p = g_pos[wi];
    int cx, cy, cz; cellCoord(p.x, p.y, p.z, cx, cy, cz);
    float sx = 0.f, sy = 0.f, sz = 0.f;
    int x0 = cx > 0 ? cx - 1 : 0;
    int x1 = cx < NC - 1 ? cx + 1 : NC - 1;
    #pragma unroll
    for (int dz = -1; dz <= 1; dz++) {
        int z = cz + dz; if (z < 0 || z >= NC) continue;
        #pragma unroll
        for (int dy = -1; dy <= 1; dy++) {
            int y = cy + dy; if (y < 0 || y >= NC) continue;
            int c0 = (z * NC + y) * NC + x0;
            int s = g_cellStart[c0];
            int e = g_cellStart[c0 + (x1 - x0) + 1];
            for (int j = s + lane; j < e; j += 32) {
                float4 q = g_pos[j];
                float dx = p.x - q.x, dyv = p.y - q.y, dzv = p.z - q.z;
                float d2e = fmaf(dx, dx, fmaf(dyv, dyv, fmaf(dzv, dzv, EPS_C)));
                float rinv = rsqrtf(d2e);
                float t = fmaxf(fmaf(-d2e, rinv, RADIUS_C), 0.0f);
                // self pair: diff = 0 -> contributes 0
                float c = ((p.w + q.w) * (t * t)) * rinv;
                sx = fmaf(c, dx,  sx);
                sy = fmaf(c, dyv, sy);
                sz = fmaf(c, dzv, sz);
            }
        }
    }
    sx = warp_sum(sx); sy = warp_sum(sy); sz = warp_sum(sz);
    if (lane == 0) {
        int orig = g_origIdx[wi];
        float nx = p.x + sx, ny = p.y + sy, nz = p.z + sz;  // RELAXATION = 1
        g_posTmp[orig] = make_float4(nx, ny, nz, 0.0f);
        int cid = cellId(nx, ny, nz);
        g_cid[orig] = cid;
        atomicAdd(&g_hist[cid], 1);
        if (last) {
            g_vel[orig] = make_float4((nx - locs[3*orig+0]) * INV_DT_C,
                                      (ny - locs[3*orig+1]) * INV_DT_C,
                                      (nz - locs[3*orig+2]) * INV_DT_C, 0.0f);
            out_pred[3*orig+0] = nx;
            out_pred[3*orig+1] = ny;
            out_pred[3*orig+2] = nz;
        }
    }
}

// XSPH viscosity, warp per sorted slot on final positions + sorted velocities.
// Self term cancels exactly in (sum_j w v_j) - wsum*v_i.
__global__ void __launch_bounds__(PASS_BLOCK) visc_cell_kernel(
        float* __restrict__ out_vel) {
    int wi   = blockIdx.x * (PASS_BLOCK / 32) + (threadIdx.x >> 5);
    int lane = threadIdx.x & 31;
    float4 p = g_pos[wi];
    int cx, cy, cz; cellCoord(p.x, p.y, p.z, cx, cy, cz);
    float wsum = 0.f, wx = 0.f, wy = 0.f, wz = 0.f;  // unscaled t^3 weights
    int x0 = cx > 0 ? cx - 1 : 0;
    int x1 = cx < NC - 1 ? cx + 1 : NC - 1;
    #pragma unroll
    for (int dz = -1; dz <= 1; dz++) {
        int z = cz + dz; if (z < 0 || z >= NC) continue;
        #pragma unroll
        for (int dy = -1; dy <= 1; dy++) {
            int y = cy + dy; if (y < 0 || y >= NC) continue;
            int c0 = (z * NC + y) * NC + x0;
            int s = g_cellStart[c0];
            int e = g_cellStart[c0 + (x1 - x0) + 1];
            for (int j = s + lane; j < e; j += 32) {
                float4 q = g_pos[j];
                float dx = p.x - q.x, dyv = p.y - q.y, dzv = p.z - q.z;
                float d2e = fmaf(dx, dx, fmaf(dyv, dyv, fmaf(dzv, dzv, EPS_C)));
                float rinv = rsqrtf(d2e);
                float t = fmaxf(fmaf(-d2e, rinv, RADIUS_C), 0.0f);
                float w = (t * t) * t;
                float4 vj = g_velS[j];
                wsum += w;
                wx = fmaf(w, vj.x, wx);
                wy = fmaf(w, vj.y, wy);
                wz = fmaf(w, vj.z, wz);
            }
        }
    }
    wsum = warp_sum(wsum); wx = warp_sum(wx); wy = warp_sum(wy); wz = warp_sum(wz);
    if (lane == 0) {
        int orig = g_origIdx[wi];
        float4 v = g_velS[wi];
        const float kk = (VISC_C * DT_C / REST_C) * SPIKY_C;  // fold spiky scale
        float nx = v.x + kk * (wx - wsum * v.x);
        float ny = v.y + kk * (wy - wsum * v.y);
        float nz = v.z + kk * (wz - wsum * v.z);
        float3 c = cap_mag(nx, ny, nz);
        out_vel[3*orig+0] = c.x;
        out_vel[3*orig+1] = c.y;
        out_vel[3*orig+2] = c.z;
    }
}

// ---------------- launcher ----------------
extern "C" void kernel_launch(void* const* d_in, const int* in_sizes, int n_in,
                              void* d_out, int out_size) {
    const float* locs = (const float*)d_in[0];
    const float* vel  = (const float*)d_in[1];
    float* out = (float*)d_out;
    float* out_pred = out;                 // [1,4096,3]
    float* out_vel  = out + 3 * NP;        // [1,4096,3]

    // init also histograms predicted positions (g_hist is zero at entry;
    // each scan_kernel re-zeroes it, so every call/replay sees the same state)
    init_kernel<<<NP / 256, 256>>>(locs, vel);

    for (int it = 0; it < 3; it++) {
        scan_kernel<<<1, 1024>>>();
        scatter_kernel<<<NP / 256, 256>>>(0);
        rho_cell_kernel<<<PASS_GRID, PASS_BLOCK>>>();
        // delta histograms its output positions for the next build
        delta_cell_kernel<<<PASS_GRID, PASS_BLOCK>>>(it == 2, locs, out_pred);
    }
    // final neighbor structure on final positions, with velocities gathered
    scan_kernel<<<1, 1024>>>();
    scatter_kernel<<<NP / 256, 256>>>(1);
    visc_cell_kernel<<<PASS_GRID, PASS_BLOCK>>>(out_vel);
}

// round 10
// speedup vs baseline: 1.2063x; 1.0826x over previous
#include <cuda_runtime.h>
#include <math.h>

// ---------------- simulation constants (mirror reference) ----------------
#define NP          4096
#define NC          10                    // cells per axis (cell size = RADIUS)
#define NCELL       (NC * NC * NC)        // 1000
#define RADIUS_C    0.1f
#define DT_C        (1.0f/60.0f)
#define INV_DT_C    60.0f
#define MAX_VEL_C   3.0f                  // 0.5*0.1/DT
#define VISC_C      60.0f
#define REST_C      17510.1f
#define STIFF_C     2.99e-11f
#define EPS_C       1e-8f
// 15 / (pi * R^6)
#define SPIKY_C     (15.0f / (3.14159265358979323846f * 1e-6f))

#define PASS_BLOCK  256                   // 8 warps; 2 warps per particle
#define PPB         4                     // particles per block
#define PASS_GRID   (NP / PPB)            // 1024 blocks -> 8192 warps total

// ---------------- scratch state (no allocations allowed) -----------------
__device__ float4 g_posTmp[NP];   // canonical UNSORTED positions (w unused)
__device__ float4 g_pos[NP];      // cell-sorted positions; .w carries lambda'
__device__ float4 g_velS[NP];     // cell-sorted raw velocities (visc pass)
__device__ float4 g_vel[NP];      // unsorted raw new_vel (written by last delta)
__device__ int    g_origIdx[NP];  // sorted slot -> original index
__device__ int    g_cellStart[NCELL + 1];

// ---------------- helpers ----------------
__device__ __forceinline__ int clampi(int v, int lo, int hi) {
    return v < lo ? lo : (v > hi ? hi : v);
}
__device__ __forceinline__ int cellId(float x, float y, float z) {
    int cx = clampi(__float2int_rd(x * (float)NC), 0, NC - 1);
    int cy = clampi(__float2int_rd(y * (float)NC), 0, NC - 1);
    int cz = clampi(__float2int_rd(z * (float)NC), 0, NC - 1);
    return (cz * NC + cy) * NC + cx;
}
__device__ __forceinline__ float warp_sum(float v) {
    #pragma unroll
    for (int o = 16; o > 0; o >>= 1) v += __shfl_xor_sync(0xFFFFFFFFu, v, o);
    return v;
}
__device__ __forceinline__ float3 cap_mag(float x, float y, float z) {
    float vv = sqrtf(x*x + y*y + z*z);
    float s  = fminf(MAX_VEL_C / (vv + 1e-4f), 1.0f);
    return make_float3(x*s, y*s, z*s);
}

// Build flattened candidate ranges for particle p (warp-collective).
// 9 lanes load segment bounds in parallel; warp scan builds prefix offsets.
// seg_s[0..8] = segment starts, seg_p[0..9] = prefix (seg_p[9] = T).
// Both parity warps of a particle call this; they write identical values.
__device__ __forceinline__ int build_ranges(float4 p, int lane,
                                            int* seg_s, int* seg_p) {
    int cx = clampi(__float2int_rd(p.x * (float)NC), 0, NC - 1);
    int cy = clampi(__float2int_rd(p.y * (float)NC), 0, NC - 1);
    int cz = clampi(__float2int_rd(p.z * (float)NC), 0, NC - 1);
    int x0 = cx > 0 ? cx - 1 : 0;
    int x1 = cx < NC - 1 ? cx + 1 : NC - 1;
    int xlen = x1 - x0 + 1;

    int s_ = 0, len = 0;
    if (lane < 9) {
        int ry = cy + (lane % 3) - 1;
        int rz = cz + (lane / 3) - 1;
        if (ry >= 0 && ry < NC && rz >= 0 && rz < NC) {
            int c0 = (rz * NC + ry) * NC + x0;
            s_  = g_cellStart[c0];
            len = g_cellStart[c0 + xlen] - s_;
        }
    }
    int pr = len;
    #pragma unroll
    for (int o = 1; o < 16; o <<= 1) {
        int t = __shfl_up_sync(0xFFFFFFFFu, pr, o);
        if (lane >= o) pr += t;
    }
    int excl = pr - len;
    int T = __shfl_sync(0xFFFFFFFFu, pr, 8);   // inclusive over lanes 0..8
    if (lane < 10) {
        seg_p[lane] = (lane < 9) ? excl : T;   // seg_p[9] = T sentinel
        if (lane < 9) seg_s[lane] = s_;
    }
    __syncwarp();
    return T;
}

// ---------------- kernels ----------------
// FULLY FUSED build: (optional init from locs/vel) + histogram + scan +
// scatter, in one 1024-thread block. Each thread owns 4 particles and keeps
// their data in registers across phases. No global histogram/cid state.
__global__ void __launch_bounds__(1024) build_kernel(
        int first, int copyVel,
        const float* __restrict__ locs, const float* __restrict__ vel) {
    __shared__ int hist[1024];              // histogram, then reused as cursor
    __shared__ int scanb[1024];
    int tid = threadIdx.x;
    hist[tid] = 0;
    __syncthreads();

    float4 myp[4];
    int    mycid[4];
    #pragma unroll
    for (int u = 0; u < 4; u++) {
        int i = tid + u * 1024;
        float4 p;
        if (first) {
            float vx = vel[3*i+0];
            float vy = vel[3*i+1] - 9.8f * DT_C;
            float vz = vel[3*i+2];
            float3 v = cap_mag(vx, vy, vz);
            p = make_float4(locs[3*i+0] + DT_C * v.x,
                            locs[3*i+1] + DT_C * v.y,
                            locs[3*i+2] + DT_C * v.z, 0.0f);
            g_posTmp[i] = p;                // canonical unsorted copy
        } else {
            p = g_posTmp[i];
        }
        myp[u]   = p;
        mycid[u] = cellId(p.x, p.y, p.z);
        atomicAdd(&hist[mycid[u]], 1);
    }
    __syncthreads();

    int v = hist[tid];
    scanb[tid] = v;
    __syncthreads();
    #pragma unroll
    for (int off = 1; off < 1024; off <<= 1) {
        int t = (tid >= off) ? scanb[tid - off] : 0;
        __syncthreads();
        scanb[tid] += t;
        __syncthreads();
    }
    int excl = scanb[tid] - v;              // exclusive scan
    hist[tid] = excl;                       // reuse as scatter cursor
    if (tid <= NCELL) g_cellStart[tid] = excl;  // cellStart[NCELL] == NP
    __syncthreads();

    #pragma unroll
    for (int u = 0; u < 4; u++) {
        int i = tid + u * 1024;
        int slot = atomicAdd(&hist[mycid[u]], 1);
        g_pos[slot] = make_float4(myp[u].x, myp[u].y, myp[u].z, 0.0f);
        g_origIdx[slot] = i;
        if (copyVel) g_velS[slot] = g_vel[i];
    }
}

// density + lambda; 2 warps per particle (parity-split candidate list).
// Writes pre-scaled lambda' = -3*SPIKY_C*lambda into g_pos[wi].w.
__global__ void __launch_bounds__(PASS_BLOCK) rho_cell_kernel() {
    __shared__ int   seg_s[PPB][16], seg_p[PPB][16];
    __shared__ float red[PPB][4];
    int w    = threadIdx.x >> 5;
    int lane = threadIdx.x & 31;
    int pg   = w >> 1;                      // particle within block
    int par  = w & 1;                       // parity warp
    int wi   = blockIdx.x * PPB + pg;
    float4 p = g_pos[wi];
    int T = build_ranges(p, lane, seg_s[pg], seg_p[pg]);

    float sum = 0.0f;                       // unscaled sum of t^3 (incl. self)
    int k = 0;
    for (int f = lane + 32 * par; f < T; f += 64) {
        while (seg_p[pg][k+1] <= f) k++;    // monotonic: amortized O(1)
        int j = seg_s[pg][k] + (f - seg_p[pg][k]);
        float4 q = g_pos[j];
        float dx = p.x - q.x, dyv = p.y - q.y, dzv = p.z - q.z;
        float d2e = fmaf(dx, dx, fmaf(dyv, dyv, fmaf(dzv, dzv, EPS_C)));
        float rinv = rsqrtf(d2e);
        float t = fmaxf(fmaf(-d2e, rinv, RADIUS_C), 0.0f);  // max(R-d,0)
        sum = fmaf(t * t, t, sum);
    }
    sum = warp_sum(sum);
    if (par == 1 && lane == 0) red[pg][0] = sum;
    __syncthreads();
    if (par == 0 && lane == 0) {
        sum += red[pg][0];
        // subtract self term (d2e = EPS_C), identical op sequence
        float rs = rsqrtf(EPS_C);
        float ts = fmaxf(fmaf(-EPS_C, rs, RADIUS_C), 0.0f);
        float rho = (sum - (ts * ts) * ts) * SPIKY_C;
        float lam = -(rho - REST_C) * STIFF_C;
        g_pos[wi].w = lam * (-3.0f * SPIKY_C);      // pre-scaled lambda'
    }
}

// position correction; 2 warps per particle. Writes unsorted g_posTmp.
__global__ void __launch_bounds__(PASS_BLOCK) delta_cell_kernel(
        int last, const float* __restrict__ locs, float* __restrict__ out_pred) {
    __shared__ int   seg_s[PPB][16], seg_p[PPB][16];
    __shared__ float red[PPB][4];
    int w    = threadIdx.x >> 5;
    int lane = threadIdx.x & 31;
    int pg   = w >> 1;
    int par  = w & 1;
    int wi   = blockIdx.x * PPB + pg;
    float4 p = g_pos[wi];
    int T = build_ranges(p, lane, seg_s[pg], seg_p[pg]);

    float sx = 0.f, sy = 0.f, sz = 0.f;
    int k = 0;
    for (int f = lane + 32 * par; f < T; f += 64) {
        while (seg_p[pg][k+1] <= f) k++;
        int j = seg_s[pg][k] + (f - seg_p[pg][k]);
        float4 q = g_pos[j];
        float dx = p.x - q.x, dyv = p.y - q.y, dzv = p.z - q.z;
        float d2e = fmaf(dx, dx, fmaf(dyv, dyv, fmaf(dzv, dzv, EPS_C)));
        float rinv = rsqrtf(d2e);
        float t = fmaxf(fmaf(-d2e, rinv, RADIUS_C), 0.0f);
        // self pair: diff = 0 -> contributes 0
        float c = ((p.w + q.w) * (t * t)) * rinv;
        sx = fmaf(c, dx,  sx);
        sy = fmaf(c, dyv, sy);
        sz = fmaf(c, dzv, sz);
    }
    sx = warp_sum(sx); sy = warp_sum(sy); sz = warp_sum(sz);
    if (par == 1 && lane == 0) {
        red[pg][0] = sx; red[pg][1] = sy; red[pg][2] = sz;
    }
    __syncthreads();
    if (par == 0 && lane == 0) {
        sx += red[pg][0]; sy += red[pg][1]; sz += red[pg][2];
        int orig = g_origIdx[wi];
        float nx = p.x + sx, ny = p.y + sy, nz = p.z + sz;  // RELAXATION = 1
        g_posTmp[orig] = make_float4(nx, ny, nz, 0.0f);
        if (last) {
            g_vel[orig] = make_float4((nx - locs[3*orig+0]) * INV_DT_C,
                                      (ny - locs[3*orig+1]) * INV_DT_C,
                                      (nz - locs[3*orig+2]) * INV_DT_C, 0.0f);
            out_pred[3*orig+0] = nx;
            out_pred[3*orig+1] = ny;
            out_pred[3*orig+2] = nz;
        }
    }
}

// XSPH viscosity; 2 warps per particle on final positions + sorted velocities.
// Self term cancels exactly in (sum_j w v_j) - wsum*v_i.
__global__ void __launch_bounds__(PASS_BLOCK) visc_cell_kernel(
        float* __restrict__ out_vel) {
    __shared__ int   seg_s[PPB][16], seg_p[PPB][16];
    __shared__ float red[PPB][4];
    int w    = threadIdx.x >> 5;
    int lane = threadIdx.x & 31;
    int pg   = w >> 1;
    int par  = w & 1;
    int wi   = blockIdx.x * PPB + pg;
    float4 p = g_pos[wi];
    int T = build_ranges(p, lane, seg_s[pg], seg_p[pg]);

    float wsum = 0.f, wx = 0.f, wy = 0.f, wz = 0.f;  // unscaled t^3 weights
    int k = 0;
    for (int f = lane + 32 * par; f < T; f += 64) {
        while (seg_p[pg][k+1] <= f) k++;
        int j = seg_s[pg][k] + (f - seg_p[pg][k]);
        float4 q = g_pos[j];
        float dx = p.x - q.x, dyv = p.y - q.y, dzv = p.z - q.z;
        float d2e = fmaf(dx, dx, fmaf(dyv, dyv, fmaf(dzv, dzv, EPS_C)));
        float rinv = rsqrtf(d2e);
        float t = fmaxf(fmaf(-d2e, rinv, RADIUS_C), 0.0f);
        float wgt = (t * t) * t;
        float4 vj = g_velS[j];
        wsum += wgt;
        wx = fmaf(wgt, vj.x, wx);
        wy = fmaf(wgt, vj.y, wy);
        wz = fmaf(wgt, vj.z, wz);
    }
    wsum = warp_sum(wsum); wx = warp_sum(wx); wy = warp_sum(wy); wz = warp_sum(wz);
    if (par == 1 && lane == 0) {
        red[pg][0] = wsum; red[pg][1] = wx; red[pg][2] = wy; red[pg][3] = wz;
    }
    __syncthreads();
    if (par == 0 && lane == 0) {
        wsum += red[pg][0]; wx += red[pg][1]; wy += red[pg][2]; wz += red[pg][3];
        int orig = g_origIdx[wi];
        float4 v = g_velS[wi];
        const float kk = (VISC_C * DT_C / REST_C) * SPIKY_C;  // fold spiky scale
        float nx = v.x + kk * (wx - wsum * v.x);
        float ny = v.y + kk * (wy - wsum * v.y);
        float nz = v.z + kk * (wz - wsum * v.z);
        float3 c = cap_mag(nx, ny, nz);
        out_vel[3*orig+0] = c.x;
        out_vel[3*orig+1] = c.y;
        out_vel[3*orig+2] = c.z;
    }
}

// ---------------- launcher ----------------
extern "C" void kernel_launch(void* const* d_in, const int* in_sizes, int n_in,
                              void* d_out, int out_size) {
    const float* locs = (const float*)d_in[0];
    const float* vel  = (const float*)d_in[1];
    float* out = (float*)d_out;
    float* out_pred = out;                 // [1,4096,3]
    float* out_vel  = out + 3 * NP;        // [1,4096,3]

    // iter 1: fused init+build, then rho/delta
    build_kernel<<<1, 1024>>>(1, 0, locs, vel);
    rho_cell_kernel<<<PASS_GRID, PASS_BLOCK>>>();
    delta_cell_kernel<<<PASS_GRID, PASS_BLOCK>>>(0, locs, out_pred);
    // iter 2
    build_kernel<<<1, 1024>>>(0, 0, locs, vel);
    rho_cell_kernel<<<PASS_GRID, PASS_BLOCK>>>();
    delta_cell_kernel<<<PASS_GRID, PASS_BLOCK>>>(0, locs, out_pred);
    // iter 3 (final): delta also emits pred + raw new_vel
    build_kernel<<<1, 1024>>>(0, 0, locs, vel);
    rho_cell_kernel<<<PASS_GRID, PASS_BLOCK>>>();
    delta_cell_kernel<<<PASS_GRID, PASS_BLOCK>>>(1, locs, out_pred);
    // final neighbor structure on final positions, with velocities gathered
    build_kernel<<<1, 1024>>>(0, 1, locs, vel);
    visc_cell_kernel<<<PASS_GRID, PASS_BLOCK>>>(out_vel);
}